// round 8
// baseline (speedup 1.0000x reference)
#include <cuda_runtime.h>
#include <cuda_fp16.h>
#include <math.h>
#include <stdint.h>

#define BATCH 8
#define CIN   256
#define NSP   4096
#define CKV   128
#define TN    64
#define NT    (NSP / TN)

// ---------------- scratch (allocation-free rule) ----------------
__device__ __half g_Qh[BATCH * NSP * CKV];
__device__ __half g_Ql[BATCH * NSP * CKV];
__device__ __half g_Kh[BATCH * NSP * CKV];
__device__ __half g_Kl[BATCH * NSP * CKV];
__device__ __half g_V [BATCH * CKV * NSP];   // transposed: [b][v][n]
__device__ float  g_Y [BATCH * NSP * CKV];

// ---------------- smem layout (bytes), rows padded +16B for LDSM CF ----------
#define KHOFF 0u         // 64 x 272
#define KLOFF 17408u     // 64 x 272
#define VOFF  34816u     // 128 x 144
#define QHOFF 53248u     // 128 x 272
#define QLOFF 88064u     // 128 x 272
#define SMEM_ATTN 122880u

__device__ __forceinline__ uint32_t smem_u32(const void* p) {
    uint32_t a;
    asm("{ .reg .u64 t; cvta.to.shared.u64 t, %1; cvt.u32.u64 %0, t; }"
        : "=r"(a) : "l"(p));
    return a;
}
__device__ __forceinline__ void ldsm4(uint32_t* r, uint32_t addr) {
    asm volatile("ldmatrix.sync.aligned.m8n8.x4.shared.b16 {%0,%1,%2,%3}, [%4];"
                 : "=r"(r[0]), "=r"(r[1]), "=r"(r[2]), "=r"(r[3]) : "r"(addr));
}
__device__ __forceinline__ void mma16816(float* c, const uint32_t* a,
                                         uint32_t b0, uint32_t b1) {
    asm volatile(
        "mma.sync.aligned.m16n8k16.row.col.f32.f16.f16.f32 "
        "{%0,%1,%2,%3}, {%4,%5,%6,%7}, {%8,%9}, {%0,%1,%2,%3};"
        : "+f"(c[0]), "+f"(c[1]), "+f"(c[2]), "+f"(c[3])
        : "r"(a[0]), "r"(a[1]), "r"(a[2]), "r"(a[3]), "r"(b0), "r"(b1));
}
__device__ __forceinline__ uint32_t packh2(float x, float y) {
    __half2 h = __floats2half2_rn(x, y);
    return *reinterpret_cast<uint32_t*>(&h);
}

// ---------------------------------------------------------------------------
// Kernel 1: fused QKV projection -> fp16 (Q,K split hi/lo; V plain, transposed)
// ---------------------------------------------------------------------------
__global__ __launch_bounds__(256) void proj_qkv_kernel(
    const float* __restrict__ x,
    const float* __restrict__ theta_w, const float* __restrict__ theta_b,
    const float* __restrict__ phi_w,   const float* __restrict__ phi_b,
    const float* __restrict__ gw,      const float* __restrict__ gb)
{
    const int b  = blockIdx.z;
    const int n0 = blockIdx.x * 128;
    const int p  = blockIdx.y;

    const float* w  = (p == 0) ? theta_w : (p == 1) ? phi_w : gw;
    const float* bs = (p == 0) ? theta_b : (p == 1) ? phi_b : gb;

    __shared__ float xs[32][128];
    __shared__ float ws[32][129];

    const int tid = threadIdx.x;
    const int tx  = tid & 15;
    const int ty  = tid >> 4;

    float acc[8][8];
#pragma unroll
    for (int i = 0; i < 8; i++)
#pragma unroll
        for (int j = 0; j < 8; j++) acc[i][j] = 0.f;

    for (int c0 = 0; c0 < CIN; c0 += 32) {
        {
            const int n4 = tid & 31;
            const int cr = tid >> 5;
#pragma unroll
            for (int r = 0; r < 4; r++) {
                const int c = cr + r * 8;
                const float4 v = *reinterpret_cast<const float4*>(
                    &x[(((size_t)b * CIN) + c0 + c) * NSP + n0 + n4 * 4]);
                *reinterpret_cast<float4*>(&xs[c][n4 * 4]) = v;
            }
        }
        {
            const int cl = tid & 31;
            const int kr = tid >> 5;
#pragma unroll
            for (int r = 0; r < 16; r++) {
                const int k = kr + r * 8;
                ws[cl][k] = w[k * CIN + c0 + cl];
            }
        }
        __syncthreads();

#pragma unroll 8
        for (int c = 0; c < 32; c++) {
            float a[8], bb[8];
#pragma unroll
            for (int i = 0; i < 8; i++) a[i]  = xs[c][i * 16 + ty];
#pragma unroll
            for (int j = 0; j < 8; j++) bb[j] = ws[c][j * 16 + tx];
#pragma unroll
            for (int i = 0; i < 8; i++)
#pragma unroll
                for (int j = 0; j < 8; j++)
                    acc[i][j] = fmaf(a[i], bb[j], acc[i][j]);
        }
        __syncthreads();
    }

#pragma unroll
    for (int j = 0; j < 8; j++) {
        const int k  = j * 16 + tx;
        const float bj = __ldg(&bs[k]);
#pragma unroll
        for (int i = 0; i < 8; i++) {
            const int n = n0 + i * 16 + ty;
            const float val = acc[i][j] + bj;
            if (p == 2) {
                g_V[(((size_t)b * CKV) + k) * NSP + n] = __float2half_rn(val);
            } else {
                const __half hi = __float2half_rn(val);
                const __half lo = __float2half_rn(val - __half2float(hi));
                const size_t idx = (((size_t)b * NSP) + n) * CKV + k;
                if (p == 0) { g_Qh[idx] = hi; g_Ql[idx] = lo; }
                else        { g_Kh[idx] = hi; g_Kl[idx] = lo; }
            }
        }
    }
}

// ---------------------------------------------------------------------------
// Kernel 2: flash attention via mma.sync (HMMA fallback), split-fp16.
// 256 thr = 8 warps; warp w owns query rows [16w,16w+16), full 64-col S tile,
// full 128-col O tile. Online softmax, O rescale in registers, P stays in regs.
// ---------------------------------------------------------------------------
__global__ __launch_bounds__(256, 1) void attn_hmma_kernel()
{
    extern __shared__ char sm[];
    const uint32_t smb = smem_u32(sm);

    const int b    = blockIdx.y;
    const int n0   = blockIdx.x * 128;
    const int tid  = threadIdx.x;
    const int wrp  = tid >> 5;
    const int lane = tid & 31;
    const uint32_t grp  = (uint32_t)(lane >> 3);
    const uint32_t lrow = (uint32_t)(lane & 7);
    const int quad = lane & 3;
    const int r1   = lane >> 2;

    // ---- load Q tile (hi/lo) into padded smem ----
    {
        const size_t qb = ((size_t)b * NSP + n0) * CKV;
#pragma unroll
        for (int i = 0; i < 8; i++) {
            const int idx = tid + i * 256;
            const int row = idx >> 4, c16 = idx & 15;
            const uint32_t so = (uint32_t)row * 272u + (uint32_t)c16 * 16u;
            *reinterpret_cast<uint4*>(sm + QHOFF + so) =
                *reinterpret_cast<const uint4*>(&g_Qh[qb + (size_t)row * CKV + c16 * 8]);
            *reinterpret_cast<uint4*>(sm + QLOFF + so) =
                *reinterpret_cast<const uint4*>(&g_Ql[qb + (size_t)row * CKV + c16 * 8]);
        }
    }

    float o[16][4];
#pragma unroll
    for (int v = 0; v < 16; v++)
#pragma unroll
        for (int j = 0; j < 4; j++) o[v][j] = 0.f;
    float mA = -INFINITY, mB = -INFINITY, lA = 0.f, lB = 0.f;

    const uint32_t arow = (uint32_t)(wrp * 16) + lrow + (grp & 1u) * 8u;
    const uint32_t acol = (grp >> 1) * 16u;

    for (int t = 0; t < NT; t++) {
        __syncthreads();
        // ---- load K (hi/lo) and V tiles ----
        {
            const size_t kb = ((size_t)b * NSP + (size_t)t * TN) * CKV;
#pragma unroll
            for (int i = 0; i < 4; i++) {
                const int idx = tid + i * 256;
                const int row = idx >> 4, c16 = idx & 15;
                const uint32_t so = (uint32_t)row * 272u + (uint32_t)c16 * 16u;
                *reinterpret_cast<uint4*>(sm + KHOFF + so) =
                    *reinterpret_cast<const uint4*>(&g_Kh[kb + (size_t)row * CKV + c16 * 8]);
                *reinterpret_cast<uint4*>(sm + KLOFF + so) =
                    *reinterpret_cast<const uint4*>(&g_Kl[kb + (size_t)row * CKV + c16 * 8]);
            }
#pragma unroll
            for (int i = 0; i < 4; i++) {
                const int idx = tid + i * 256;
                const int vr = idx >> 3, c = idx & 7;
                const uint32_t so = (uint32_t)vr * 144u + (uint32_t)c * 16u;
                *reinterpret_cast<uint4*>(sm + VOFF + so) =
                    *reinterpret_cast<const uint4*>(
                        &g_V[(((size_t)b * CKV) + vr) * NSP + (size_t)t * TN + c * 8]);
            }
        }
        __syncthreads();

        // ---- S = Qh.Kh^T + Ql.Kh^T + Qh.Kl^T ----
        float s[8][4];
#pragma unroll
        for (int n = 0; n < 8; n++)
#pragma unroll
            for (int j = 0; j < 4; j++) s[n][j] = 0.f;

#pragma unroll
        for (int kk = 0; kk < 8; kk++) {
            uint32_t aqh[4], aql[4];
            const uint32_t ao = arow * 272u + (uint32_t)kk * 32u + acol;
            ldsm4(aqh, smb + QHOFF + ao);
            ldsm4(aql, smb + QLOFF + ao);
#pragma unroll
            for (int nt2 = 0; nt2 < 4; nt2++) {
                uint32_t kh[4], kl[4];
                const uint32_t brow = (uint32_t)(nt2 * 16) + lrow + (grp >> 1) * 8u;
                const uint32_t bo = brow * 272u + (uint32_t)kk * 32u + (grp & 1u) * 16u;
                ldsm4(kh, smb + KHOFF + bo);
                ldsm4(kl, smb + KLOFF + bo);
                mma16816(s[2 * nt2],     aqh, kh[0], kh[1]);
                mma16816(s[2 * nt2 + 1], aqh, kh[2], kh[3]);
                mma16816(s[2 * nt2],     aql, kh[0], kh[1]);
                mma16816(s[2 * nt2 + 1], aql, kh[2], kh[3]);
                mma16816(s[2 * nt2],     aqh, kl[0], kl[1]);
                mma16816(s[2 * nt2 + 1], aqh, kl[2], kl[3]);
            }
        }

        // ---- online softmax (rows A: r1, B: r1+8) ----
        float tmA = -INFINITY, tmB = -INFINITY;
#pragma unroll
        for (int n = 0; n < 8; n++) {
            tmA = fmaxf(tmA, fmaxf(s[n][0], s[n][1]));
            tmB = fmaxf(tmB, fmaxf(s[n][2], s[n][3]));
        }
        tmA = fmaxf(tmA, __shfl_xor_sync(0xffffffffu, tmA, 1));
        tmA = fmaxf(tmA, __shfl_xor_sync(0xffffffffu, tmA, 2));
        tmB = fmaxf(tmB, __shfl_xor_sync(0xffffffffu, tmB, 1));
        tmB = fmaxf(tmB, __shfl_xor_sync(0xffffffffu, tmB, 2));

        const float nmA = fmaxf(mA, tmA), nmB = fmaxf(mB, tmB);
        const float cA = __expf(mA - nmA), cB = __expf(mB - nmB);
        mA = nmA; mB = nmB;

        uint32_t aph[4][4], apl[4][4];
        float sumA = 0.f, sumB = 0.f;
#pragma unroll
        for (int n = 0; n < 8; n++) {
            const float e0 = __expf(s[n][0] - mA);
            const float e1 = __expf(s[n][1] - mA);
            const float e2 = __expf(s[n][2] - mB);
            const float e3 = __expf(s[n][3] - mB);
            sumA += e0 + e1; sumB += e2 + e3;
            const __half h0 = __float2half_rn(e0), h1 = __float2half_rn(e1);
            const __half h2 = __float2half_rn(e2), h3 = __float2half_rn(e3);
            const float l0 = e0 - __half2float(h0), f1 = e1 - __half2float(h1);
            const float l2 = e2 - __half2float(h2), f3 = e3 - __half2float(h3);
            const int kk = n >> 1, hi = (n & 1) ? 2 : 0;
            aph[kk][hi]     = packh2(e0, e1);
            aph[kk][hi + 1] = packh2(e2, e3);
            apl[kk][hi]     = packh2(l0, f1);
            apl[kk][hi + 1] = packh2(l2, f3);
        }
        lA = lA * cA + sumA;
        lB = lB * cB + sumB;
#pragma unroll
        for (int v = 0; v < 16; v++) {
            o[v][0] *= cA; o[v][1] *= cA; o[v][2] *= cB; o[v][3] *= cB;
        }

        // ---- O += Ph.V + Pl.V ----
#pragma unroll
        for (int kk = 0; kk < 4; kk++) {
#pragma unroll
            for (int vt2 = 0; vt2 < 8; vt2++) {
                uint32_t bv[4];
                const uint32_t vrow = (uint32_t)(vt2 * 16) + lrow + (grp >> 1) * 8u;
                const uint32_t vo = vrow * 144u + (uint32_t)kk * 32u + (grp & 1u) * 16u;
                ldsm4(bv, smb + VOFF + vo);
                mma16816(o[2 * vt2],     aph[kk], bv[0], bv[1]);
                mma16816(o[2 * vt2 + 1], aph[kk], bv[2], bv[3]);
                mma16816(o[2 * vt2],     apl[kk], bv[0], bv[1]);
                mma16816(o[2 * vt2 + 1], apl[kk], bv[2], bv[3]);
            }
        }
    }

    // ---- epilogue ----
    lA += __shfl_xor_sync(0xffffffffu, lA, 1);
    lA += __shfl_xor_sync(0xffffffffu, lA, 2);
    lB += __shfl_xor_sync(0xffffffffu, lB, 1);
    lB += __shfl_xor_sync(0xffffffffu, lB, 2);
    const float invA = 1.f / lA, invB = 1.f / lB;

    const int rowA = n0 + wrp * 16 + r1;
#pragma unroll
    for (int vt = 0; vt < 16; vt++) {
        const int col = vt * 8 + quad * 2;
        float2 wa = make_float2(o[vt][0] * invA, o[vt][1] * invA);
        float2 wb = make_float2(o[vt][2] * invB, o[vt][3] * invB);
        *reinterpret_cast<float2*>(&g_Y[(((size_t)b * NSP) + rowA) * CKV + col])     = wa;
        *reinterpret_cast<float2*>(&g_Y[(((size_t)b * NSP) + rowA + 8) * CKV + col]) = wb;
    }
}

// ---------------------------------------------------------------------------
// Kernel 3: output projection (fp32, unchanged).
// ---------------------------------------------------------------------------
__global__ __launch_bounds__(256) void outproj_kernel(
    const float* __restrict__ ww, const float* __restrict__ wb,
    float* __restrict__ out)
{
    const int b  = blockIdx.z;
    const int n0 = blockIdx.x * 128;
    const int c0 = blockIdx.y * 128;

    __shared__ float As[32][129];
    __shared__ float Ws[32][129];

    const int tid = threadIdx.x;
    const int tx  = tid & 15;
    const int ty  = tid >> 4;

    float acc[8][8];
#pragma unroll
    for (int i = 0; i < 8; i++)
#pragma unroll
        for (int j = 0; j < 8; j++) acc[i][j] = 0.f;

    for (int v0 = 0; v0 < CKV; v0 += 32) {
        {
            const int vl = tid & 31;
            const int nr = tid >> 5;
#pragma unroll
            for (int r = 0; r < 16; r++) {
                const int n = nr + r * 8;
                As[vl][n] = g_Y[(((size_t)b * NSP) + n0 + n) * CKV + v0 + vl];
            }
        }
        {
            const int vl = tid & 31;
            const int cr = tid >> 5;
#pragma unroll
            for (int r = 0; r < 16; r++) {
                const int c = cr + r * 8;
                Ws[vl][c] = ww[(size_t)(c0 + c) * CKV + v0 + vl];
            }
        }
        __syncthreads();

#pragma unroll 8
        for (int v = 0; v < 32; v++) {
            float a[8], wc[8];
#pragma unroll
            for (int j = 0; j < 8; j++) a[j]  = As[v][j * 16 + tx];
#pragma unroll
            for (int i = 0; i < 8; i++) wc[i] = Ws[v][i * 16 + ty];
#pragma unroll
            for (int i = 0; i < 8; i++)
#pragma unroll
                for (int j = 0; j < 8; j++)
                    acc[i][j] = fmaf(wc[i], a[j], acc[i][j]);
        }
        __syncthreads();
    }

#pragma unroll
    for (int i = 0; i < 8; i++) {
        const int c = c0 + i * 16 + ty;
        const float bc = __ldg(&wb[c]);
#pragma unroll
        for (int j = 0; j < 8; j++) {
            out[(((size_t)b * CIN) + c) * NSP + n0 + j * 16 + tx] = acc[i][j] + bc;
        }
    }
}

// ---------------------------------------------------------------------------
extern "C" void kernel_launch(void* const* d_in, const int* in_sizes, int n_in,
                              void* d_out, int out_size)
{
    const float* x       = (const float*)d_in[0];
    const float* theta_w = (const float*)d_in[1];
    const float* theta_b = (const float*)d_in[2];
    const float* phi_w   = (const float*)d_in[3];
    const float* phi_b   = (const float*)d_in[4];
    const float* g_w     = (const float*)d_in[5];
    const float* g_b     = (const float*)d_in[6];
    const float* w_w     = (const float*)d_in[7];
    const float* w_b     = (const float*)d_in[8];
    float* out = (float*)d_out;

    proj_qkv_kernel<<<dim3(NSP / 128, 3, BATCH), 256>>>(
        x, theta_w, theta_b, phi_w, phi_b, g_w, g_b);

    cudaFuncSetAttribute(attn_hmma_kernel,
                         cudaFuncAttributeMaxDynamicSharedMemorySize,
                         (int)SMEM_ATTN);
    attn_hmma_kernel<<<dim3(NSP / 128, BATCH), 256, SMEM_ATTN>>>();

    outproj_kernel<<<dim3(NSP / 128, CIN / 128, BATCH), 256>>>(w_w, w_b, out);
}

// round 9
// speedup vs baseline: 1.0001x; 1.0001x over previous
#include <cuda_runtime.h>
#include <cuda_fp16.h>
#include <math.h>
#include <stdint.h>

#define BATCH 8
#define CIN   256
#define NSP   4096
#define CKV   128
#define TN    64
#define NT    (NSP / TN)

// ---------------- scratch (allocation-free rule) ----------------
__device__ __half g_Qh[BATCH * NSP * CKV];
__device__ __half g_Ql[BATCH * NSP * CKV];
__device__ __half g_Kh[BATCH * NSP * CKV];
__device__ __half g_Kl[BATCH * NSP * CKV];
__device__ __half g_V [BATCH * CKV * NSP];   // transposed: [b][v][n]
__device__ float  g_Y [BATCH * NSP * CKV];

// ---------------- smem layout (bytes), rows padded +16B for LDSM CF ----------
#define KHOFF 0u         // 64 x 272
#define KLOFF 17408u     // 64 x 272
#define VOFF  34816u     // 128 x 144
#define QHOFF 53248u     // 128 x 272
#define QLOFF 88064u     // 128 x 272
#define SMEM_ATTN 122880u

__device__ __forceinline__ uint32_t smem_u32(const void* p) {
    uint32_t a;
    asm("{ .reg .u64 t; cvta.to.shared.u64 t, %1; cvt.u32.u64 %0, t; }"
        : "=r"(a) : "l"(p));
    return a;
}
__device__ __forceinline__ void ldsm4(uint32_t* r, uint32_t addr) {
    asm volatile("ldmatrix.sync.aligned.m8n8.x4.shared.b16 {%0,%1,%2,%3}, [%4];"
                 : "=r"(r[0]), "=r"(r[1]), "=r"(r[2]), "=r"(r[3]) : "r"(addr));
}
__device__ __forceinline__ void mma16816(float* c, const uint32_t* a,
                                         uint32_t b0, uint32_t b1) {
    asm volatile(
        "mma.sync.aligned.m16n8k16.row.col.f32.f16.f16.f32 "
        "{%0,%1,%2,%3}, {%4,%5,%6,%7}, {%8,%9}, {%0,%1,%2,%3};"
        : "+f"(c[0]), "+f"(c[1]), "+f"(c[2]), "+f"(c[3])
        : "r"(a[0]), "r"(a[1]), "r"(a[2]), "r"(a[3]), "r"(b0), "r"(b1));
}
__device__ __forceinline__ uint32_t packh2(float x, float y) {
    __half2 h = __floats2half2_rn(x, y);
    return *reinterpret_cast<uint32_t*>(&h);
}

// ---------------------------------------------------------------------------
// Kernel 1: fused QKV projection -> fp16 (Q,K split hi/lo; V plain, transposed)
// ---------------------------------------------------------------------------
__global__ __launch_bounds__(256) void proj_qkv_kernel(
    const float* __restrict__ x,
    const float* __restrict__ theta_w, const float* __restrict__ theta_b,
    const float* __restrict__ phi_w,   const float* __restrict__ phi_b,
    const float* __restrict__ gw,      const float* __restrict__ gb)
{
    const int b  = blockIdx.z;
    const int n0 = blockIdx.x * 128;
    const int p  = blockIdx.y;

    const float* w  = (p == 0) ? theta_w : (p == 1) ? phi_w : gw;
    const float* bs = (p == 0) ? theta_b : (p == 1) ? phi_b : gb;

    __shared__ float xs[32][128];
    __shared__ float ws[32][129];

    const int tid = threadIdx.x;
    const int tx  = tid & 15;
    const int ty  = tid >> 4;

    float acc[8][8];
#pragma unroll
    for (int i = 0; i < 8; i++)
#pragma unroll
        for (int j = 0; j < 8; j++) acc[i][j] = 0.f;

    for (int c0 = 0; c0 < CIN; c0 += 32) {
        {
            const int n4 = tid & 31;
            const int cr = tid >> 5;
#pragma unroll
            for (int r = 0; r < 4; r++) {
                const int c = cr + r * 8;
                const float4 v = *reinterpret_cast<const float4*>(
                    &x[(((size_t)b * CIN) + c0 + c) * NSP + n0 + n4 * 4]);
                *reinterpret_cast<float4*>(&xs[c][n4 * 4]) = v;
            }
        }
        {
            const int cl = tid & 31;
            const int kr = tid >> 5;
#pragma unroll
            for (int r = 0; r < 16; r++) {
                const int k = kr + r * 8;
                ws[cl][k] = w[k * CIN + c0 + cl];
            }
        }
        __syncthreads();

#pragma unroll 8
        for (int c = 0; c < 32; c++) {
            float a[8], bb[8];
#pragma unroll
            for (int i = 0; i < 8; i++) a[i]  = xs[c][i * 16 + ty];
#pragma unroll
            for (int j = 0; j < 8; j++) bb[j] = ws[c][j * 16 + tx];
#pragma unroll
            for (int i = 0; i < 8; i++)
#pragma unroll
                for (int j = 0; j < 8; j++)
                    acc[i][j] = fmaf(a[i], bb[j], acc[i][j]);
        }
        __syncthreads();
    }

#pragma unroll
    for (int j = 0; j < 8; j++) {
        const int k  = j * 16 + tx;
        const float bj = __ldg(&bs[k]);
#pragma unroll
        for (int i = 0; i < 8; i++) {
            const int n = n0 + i * 16 + ty;
            const float val = acc[i][j] + bj;
            if (p == 2) {
                g_V[(((size_t)b * CKV) + k) * NSP + n] = __float2half_rn(val);
            } else {
                const __half hi = __float2half_rn(val);
                const __half lo = __float2half_rn(val - __half2float(hi));
                const size_t idx = (((size_t)b * NSP) + n) * CKV + k;
                if (p == 0) { g_Qh[idx] = hi; g_Ql[idx] = lo; }
                else        { g_Kh[idx] = hi; g_Kl[idx] = lo; }
            }
        }
    }
}

// ---------------------------------------------------------------------------
// Kernel 2: flash attention via mma.sync (HMMA fallback), split-fp16.
// 256 thr = 8 warps; warp w owns query rows [16w,16w+16), full 64-col S tile,
// full 128-col O tile. Online softmax, O rescale in registers, P stays in regs.
// ---------------------------------------------------------------------------
__global__ __launch_bounds__(256, 1) void attn_hmma_kernel()
{
    extern __shared__ char sm[];
    const uint32_t smb = smem_u32(sm);

    const int b    = blockIdx.y;
    const int n0   = blockIdx.x * 128;
    const int tid  = threadIdx.x;
    const int wrp  = tid >> 5;
    const int lane = tid & 31;
    const uint32_t grp  = (uint32_t)(lane >> 3);
    const uint32_t lrow = (uint32_t)(lane & 7);
    const int quad = lane & 3;
    const int r1   = lane >> 2;

    // ---- load Q tile (hi/lo) into padded smem ----
    {
        const size_t qb = ((size_t)b * NSP + n0) * CKV;
#pragma unroll
        for (int i = 0; i < 8; i++) {
            const int idx = tid + i * 256;
            const int row = idx >> 4, c16 = idx & 15;
            const uint32_t so = (uint32_t)row * 272u + (uint32_t)c16 * 16u;
            *reinterpret_cast<uint4*>(sm + QHOFF + so) =
                *reinterpret_cast<const uint4*>(&g_Qh[qb + (size_t)row * CKV + c16 * 8]);
            *reinterpret_cast<uint4*>(sm + QLOFF + so) =
                *reinterpret_cast<const uint4*>(&g_Ql[qb + (size_t)row * CKV + c16 * 8]);
        }
    }

    float o[16][4];
#pragma unroll
    for (int v = 0; v < 16; v++)
#pragma unroll
        for (int j = 0; j < 4; j++) o[v][j] = 0.f;
    float mA = -INFINITY, mB = -INFINITY, lA = 0.f, lB = 0.f;

    const uint32_t arow = (uint32_t)(wrp * 16) + lrow + (grp & 1u) * 8u;
    const uint32_t acol = (grp >> 1) * 16u;

    for (int t = 0; t < NT; t++) {
        __syncthreads();
        // ---- load K (hi/lo) and V tiles ----
        {
            const size_t kb = ((size_t)b * NSP + (size_t)t * TN) * CKV;
#pragma unroll
            for (int i = 0; i < 4; i++) {
                const int idx = tid + i * 256;
                const int row = idx >> 4, c16 = idx & 15;
                const uint32_t so = (uint32_t)row * 272u + (uint32_t)c16 * 16u;
                *reinterpret_cast<uint4*>(sm + KHOFF + so) =
                    *reinterpret_cast<const uint4*>(&g_Kh[kb + (size_t)row * CKV + c16 * 8]);
                *reinterpret_cast<uint4*>(sm + KLOFF + so) =
                    *reinterpret_cast<const uint4*>(&g_Kl[kb + (size_t)row * CKV + c16 * 8]);
            }
#pragma unroll
            for (int i = 0; i < 4; i++) {
                const int idx = tid + i * 256;
                const int vr = idx >> 3, c = idx & 7;
                const uint32_t so = (uint32_t)vr * 144u + (uint32_t)c * 16u;
                *reinterpret_cast<uint4*>(sm + VOFF + so) =
                    *reinterpret_cast<const uint4*>(
                        &g_V[(((size_t)b * CKV) + vr) * NSP + (size_t)t * TN + c * 8]);
            }
        }
        __syncthreads();

        // ---- S = Qh.Kh^T + Ql.Kh^T + Qh.Kl^T ----
        float s[8][4];
#pragma unroll
        for (int n = 0; n < 8; n++)
#pragma unroll
            for (int j = 0; j < 4; j++) s[n][j] = 0.f;

#pragma unroll
        for (int kk = 0; kk < 8; kk++) {
            uint32_t aqh[4], aql[4];
            const uint32_t ao = arow * 272u + (uint32_t)kk * 32u + acol;
            ldsm4(aqh, smb + QHOFF + ao);
            ldsm4(aql, smb + QLOFF + ao);
#pragma unroll
            for (int nt2 = 0; nt2 < 4; nt2++) {
                uint32_t kh[4], kl[4];
                const uint32_t brow = (uint32_t)(nt2 * 16) + lrow + (grp >> 1) * 8u;
                const uint32_t bo = brow * 272u + (uint32_t)kk * 32u + (grp & 1u) * 16u;
                ldsm4(kh, smb + KHOFF + bo);
                ldsm4(kl, smb + KLOFF + bo);
                mma16816(s[2 * nt2],     aqh, kh[0], kh[1]);
                mma16816(s[2 * nt2 + 1], aqh, kh[2], kh[3]);
                mma16816(s[2 * nt2],     aql, kh[0], kh[1]);
                mma16816(s[2 * nt2 + 1], aql, kh[2], kh[3]);
                mma16816(s[2 * nt2],     aqh, kl[0], kl[1]);
                mma16816(s[2 * nt2 + 1], aqh, kl[2], kl[3]);
            }
        }

        // ---- online softmax (rows A: r1, B: r1+8) ----
        float tmA = -INFINITY, tmB = -INFINITY;
#pragma unroll
        for (int n = 0; n < 8; n++) {
            tmA = fmaxf(tmA, fmaxf(s[n][0], s[n][1]));
            tmB = fmaxf(tmB, fmaxf(s[n][2], s[n][3]));
        }
        tmA = fmaxf(tmA, __shfl_xor_sync(0xffffffffu, tmA, 1));
        tmA = fmaxf(tmA, __shfl_xor_sync(0xffffffffu, tmA, 2));
        tmB = fmaxf(tmB, __shfl_xor_sync(0xffffffffu, tmB, 1));
        tmB = fmaxf(tmB, __shfl_xor_sync(0xffffffffu, tmB, 2));

        const float nmA = fmaxf(mA, tmA), nmB = fmaxf(mB, tmB);
        const float cA = __expf(mA - nmA), cB = __expf(mB - nmB);
        mA = nmA; mB = nmB;

        uint32_t aph[4][4], apl[4][4];
        float sumA = 0.f, sumB = 0.f;
#pragma unroll
        for (int n = 0; n < 8; n++) {
            const float e0 = __expf(s[n][0] - mA);
            const float e1 = __expf(s[n][1] - mA);
            const float e2 = __expf(s[n][2] - mB);
            const float e3 = __expf(s[n][3] - mB);
            sumA += e0 + e1; sumB += e2 + e3;
            const __half h0 = __float2half_rn(e0), h1 = __float2half_rn(e1);
            const __half h2 = __float2half_rn(e2), h3 = __float2half_rn(e3);
            const float l0 = e0 - __half2float(h0), f1 = e1 - __half2float(h1);
            const float l2 = e2 - __half2float(h2), f3 = e3 - __half2float(h3);
            const int kk = n >> 1, hi = (n & 1) ? 2 : 0;
            aph[kk][hi]     = packh2(e0, e1);
            aph[kk][hi + 1] = packh2(e2, e3);
            apl[kk][hi]     = packh2(l0, f1);
            apl[kk][hi + 1] = packh2(l2, f3);
        }
        lA = lA * cA + sumA;
        lB = lB * cB + sumB;
#pragma unroll
        for (int v = 0; v < 16; v++) {
            o[v][0] *= cA; o[v][1] *= cA; o[v][2] *= cB; o[v][3] *= cB;
        }

        // ---- O += Ph.V + Pl.V ----
#pragma unroll
        for (int kk = 0; kk < 4; kk++) {
#pragma unroll
            for (int vt2 = 0; vt2 < 8; vt2++) {
                uint32_t bv[4];
                const uint32_t vrow = (uint32_t)(vt2 * 16) + lrow + (grp >> 1) * 8u;
                const uint32_t vo = vrow * 144u + (uint32_t)kk * 32u + (grp & 1u) * 16u;
                ldsm4(bv, smb + VOFF + vo);
                mma16816(o[2 * vt2],     aph[kk], bv[0], bv[1]);
                mma16816(o[2 * vt2 + 1], aph[kk], bv[2], bv[3]);
                mma16816(o[2 * vt2],     apl[kk], bv[0], bv[1]);
                mma16816(o[2 * vt2 + 1], apl[kk], bv[2], bv[3]);
            }
        }
    }

    // ---- epilogue ----
    lA += __shfl_xor_sync(0xffffffffu, lA, 1);
    lA += __shfl_xor_sync(0xffffffffu, lA, 2);
    lB += __shfl_xor_sync(0xffffffffu, lB, 1);
    lB += __shfl_xor_sync(0xffffffffu, lB, 2);
    const float invA = 1.f / lA, invB = 1.f / lB;

    const int rowA = n0 + wrp * 16 + r1;
#pragma unroll
    for (int vt = 0; vt < 16; vt++) {
        const int col = vt * 8 + quad * 2;
        float2 wa = make_float2(o[vt][0] * invA, o[vt][1] * invA);
        float2 wb = make_float2(o[vt][2] * invB, o[vt][3] * invB);
        *reinterpret_cast<float2*>(&g_Y[(((size_t)b * NSP) + rowA) * CKV + col])     = wa;
        *reinterpret_cast<float2*>(&g_Y[(((size_t)b * NSP) + rowA + 8) * CKV + col]) = wb;
    }
}

// ---------------------------------------------------------------------------
// Kernel 3: output projection (fp32, unchanged).
// ---------------------------------------------------------------------------
__global__ __launch_bounds__(256) void outproj_kernel(
    const float* __restrict__ ww, const float* __restrict__ wb,
    float* __restrict__ out)
{
    const int b  = blockIdx.z;
    const int n0 = blockIdx.x * 128;
    const int c0 = blockIdx.y * 128;

    __shared__ float As[32][129];
    __shared__ float Ws[32][129];

    const int tid = threadIdx.x;
    const int tx  = tid & 15;
    const int ty  = tid >> 4;

    float acc[8][8];
#pragma unroll
    for (int i = 0; i < 8; i++)
#pragma unroll
        for (int j = 0; j < 8; j++) acc[i][j] = 0.f;

    for (int v0 = 0; v0 < CKV; v0 += 32) {
        {
            const int vl = tid & 31;
            const int nr = tid >> 5;
#pragma unroll
            for (int r = 0; r < 16; r++) {
                const int n = nr + r * 8;
                As[vl][n] = g_Y[(((size_t)b * NSP) + n0 + n) * CKV + v0 + vl];
            }
        }
        {
            const int vl = tid & 31;
            const int cr = tid >> 5;
#pragma unroll
            for (int r = 0; r < 16; r++) {
                const int c = cr + r * 8;
                Ws[vl][c] = ww[(size_t)(c0 + c) * CKV + v0 + vl];
            }
        }
        __syncthreads();

#pragma unroll 8
        for (int v = 0; v < 32; v++) {
            float a[8], wc[8];
#pragma unroll
            for (int j = 0; j < 8; j++) a[j]  = As[v][j * 16 + tx];
#pragma unroll
            for (int i = 0; i < 8; i++) wc[i] = Ws[v][i * 16 + ty];
#pragma unroll
            for (int i = 0; i < 8; i++)
#pragma unroll
                for (int j = 0; j < 8; j++)
                    acc[i][j] = fmaf(wc[i], a[j], acc[i][j]);
        }
        __syncthreads();
    }

#pragma unroll
    for (int i = 0; i < 8; i++) {
        const int c = c0 + i * 16 + ty;
        const float bc = __ldg(&wb[c]);
#pragma unroll
        for (int j = 0; j < 8; j++) {
            out[(((size_t)b * CIN) + c) * NSP + n0 + j * 16 + tx] = acc[i][j] + bc;
        }
    }
}

// ---------------------------------------------------------------------------
extern "C" void kernel_launch(void* const* d_in, const int* in_sizes, int n_in,
                              void* d_out, int out_size)
{
    const float* x       = (const float*)d_in[0];
    const float* theta_w = (const float*)d_in[1];
    const float* theta_b = (const float*)d_in[2];
    const float* phi_w   = (const float*)d_in[3];
    const float* phi_b   = (const float*)d_in[4];
    const float* g_w     = (const float*)d_in[5];
    const float* g_b     = (const float*)d_in[6];
    const float* w_w     = (const float*)d_in[7];
    const float* w_b     = (const float*)d_in[8];
    float* out = (float*)d_out;

    proj_qkv_kernel<<<dim3(NSP / 128, 3, BATCH), 256>>>(
        x, theta_w, theta_b, phi_w, phi_b, g_w, g_b);

    cudaFuncSetAttribute(attn_hmma_kernel,
                         cudaFuncAttributeMaxDynamicSharedMemorySize,
                         (int)SMEM_ATTN);
    attn_hmma_kernel<<<dim3(NSP / 128, BATCH), 256, SMEM_ATTN>>>();

    outproj_kernel<<<dim3(NSP / 128, CIN / 128, BATCH), 256>>>(w_w, w_b, out);
}

// round 10
// speedup vs baseline: 1.0006x; 1.0005x over previous
#include <cuda_runtime.h>
#include <cuda_fp16.h>
#include <math.h>
#include <stdint.h>

#define BATCH 8
#define CIN   256
#define NSP   4096
#define CKV   128
#define TN    64
#define NT    (NSP / TN)

// ---------------- scratch (allocation-free rule) ----------------
__device__ __half g_Qh[BATCH * NSP * CKV];
__device__ __half g_Ql[BATCH * NSP * CKV];
__device__ __half g_Kh[BATCH * NSP * CKV];
__device__ __half g_Kl[BATCH * NSP * CKV];
__device__ __half g_V [BATCH * CKV * NSP];   // transposed: [b][v][n]
__device__ float  g_Y [BATCH * NSP * CKV];

// ---------------- smem layout (bytes), rows padded +16B for LDSM CF ----------
#define KHOFF 0u         // 64 x 272
#define KLOFF 17408u     // 64 x 272
#define VOFF  34816u     // 128 x 144
#define QHOFF 53248u     // 128 x 272
#define QLOFF 88064u     // 128 x 272
#define SMEM_ATTN 122880u

__device__ __forceinline__ uint32_t smem_u32(const void* p) {
    uint32_t a;
    asm("{ .reg .u64 t; cvta.to.shared.u64 t, %1; cvt.u32.u64 %0, t; }"
        : "=r"(a) : "l"(p));
    return a;
}
__device__ __forceinline__ void ldsm4(uint32_t* r, uint32_t addr) {
    asm volatile("ldmatrix.sync.aligned.m8n8.x4.shared.b16 {%0,%1,%2,%3}, [%4];"
                 : "=r"(r[0]), "=r"(r[1]), "=r"(r[2]), "=r"(r[3]) : "r"(addr));
}
__device__ __forceinline__ void mma16816(float* c, const uint32_t* a,
                                         uint32_t b0, uint32_t b1) {
    asm volatile(
        "mma.sync.aligned.m16n8k16.row.col.f32.f16.f16.f32 "
        "{%0,%1,%2,%3}, {%4,%5,%6,%7}, {%8,%9}, {%0,%1,%2,%3};"
        : "+f"(c[0]), "+f"(c[1]), "+f"(c[2]), "+f"(c[3])
        : "r"(a[0]), "r"(a[1]), "r"(a[2]), "r"(a[3]), "r"(b0), "r"(b1));
}
__device__ __forceinline__ uint32_t packh2(float x, float y) {
    __half2 h = __floats2half2_rn(x, y);
    return *reinterpret_cast<uint32_t*>(&h);
}

// ---------------------------------------------------------------------------
// Kernel 1: fused QKV projection -> fp16 (Q,K split hi/lo; V plain, transposed)
// ---------------------------------------------------------------------------
__global__ __launch_bounds__(256) void proj_qkv_kernel(
    const float* __restrict__ x,
    const float* __restrict__ theta_w, const float* __restrict__ theta_b,
    const float* __restrict__ phi_w,   const float* __restrict__ phi_b,
    const float* __restrict__ gw,      const float* __restrict__ gb)
{
    const int b  = blockIdx.z;
    const int n0 = blockIdx.x * 128;
    const int p  = blockIdx.y;

    const float* w  = (p == 0) ? theta_w : (p == 1) ? phi_w : gw;
    const float* bs = (p == 0) ? theta_b : (p == 1) ? phi_b : gb;

    __shared__ float xs[32][128];
    __shared__ float ws[32][129];

    const int tid = threadIdx.x;
    const int tx  = tid & 15;
    const int ty  = tid >> 4;

    float acc[8][8];
#pragma unroll
    for (int i = 0; i < 8; i++)
#pragma unroll
        for (int j = 0; j < 8; j++) acc[i][j] = 0.f;

    for (int c0 = 0; c0 < CIN; c0 += 32) {
        {
            const int n4 = tid & 31;
            const int cr = tid >> 5;
#pragma unroll
            for (int r = 0; r < 4; r++) {
                const int c = cr + r * 8;
                const float4 v = *reinterpret_cast<const float4*>(
                    &x[(((size_t)b * CIN) + c0 + c) * NSP + n0 + n4 * 4]);
                *reinterpret_cast<float4*>(&xs[c][n4 * 4]) = v;
            }
        }
        {
            const int cl = tid & 31;
            const int kr = tid >> 5;
#pragma unroll
            for (int r = 0; r < 16; r++) {
                const int k = kr + r * 8;
                ws[cl][k] = w[k * CIN + c0 + cl];
            }
        }
        __syncthreads();

#pragma unroll 8
        for (int c = 0; c < 32; c++) {
            float a[8], bb[8];
#pragma unroll
            for (int i = 0; i < 8; i++) a[i]  = xs[c][i * 16 + ty];
#pragma unroll
            for (int j = 0; j < 8; j++) bb[j] = ws[c][j * 16 + tx];
#pragma unroll
            for (int i = 0; i < 8; i++)
#pragma unroll
                for (int j = 0; j < 8; j++)
                    acc[i][j] = fmaf(a[i], bb[j], acc[i][j]);
        }
        __syncthreads();
    }

#pragma unroll
    for (int j = 0; j < 8; j++) {
        const int k  = j * 16 + tx;
        const float bj = __ldg(&bs[k]);
#pragma unroll
        for (int i = 0; i < 8; i++) {
            const int n = n0 + i * 16 + ty;
            const float val = acc[i][j] + bj;
            if (p == 2) {
                g_V[(((size_t)b * CKV) + k) * NSP + n] = __float2half_rn(val);
            } else {
                const __half hi = __float2half_rn(val);
                const __half lo = __float2half_rn(val - __half2float(hi));
                const size_t idx = (((size_t)b * NSP) + n) * CKV + k;
                if (p == 0) { g_Qh[idx] = hi; g_Ql[idx] = lo; }
                else        { g_Kh[idx] = hi; g_Kl[idx] = lo; }
            }
        }
    }
}

// ---------------------------------------------------------------------------
// Kernel 2: flash attention via mma.sync (HMMA fallback), split-fp16.
// 256 thr = 8 warps; warp w owns query rows [16w,16w+16), full 64-col S tile,
// full 128-col O tile. Online softmax, O rescale in registers, P stays in regs.
// ---------------------------------------------------------------------------
__global__ __launch_bounds__(256, 1) void attn_hmma_kernel()
{
    extern __shared__ char sm[];
    const uint32_t smb = smem_u32(sm);

    const int b    = blockIdx.y;
    const int n0   = blockIdx.x * 128;
    const int tid  = threadIdx.x;
    const int wrp  = tid >> 5;
    const int lane = tid & 31;
    const uint32_t grp  = (uint32_t)(lane >> 3);
    const uint32_t lrow = (uint32_t)(lane & 7);
    const int quad = lane & 3;
    const int r1   = lane >> 2;

    // ---- load Q tile (hi/lo) into padded smem ----
    {
        const size_t qb = ((size_t)b * NSP + n0) * CKV;
#pragma unroll
        for (int i = 0; i < 8; i++) {
            const int idx = tid + i * 256;
            const int row = idx >> 4, c16 = idx & 15;
            const uint32_t so = (uint32_t)row * 272u + (uint32_t)c16 * 16u;
            *reinterpret_cast<uint4*>(sm + QHOFF + so) =
                *reinterpret_cast<const uint4*>(&g_Qh[qb + (size_t)row * CKV + c16 * 8]);
            *reinterpret_cast<uint4*>(sm + QLOFF + so) =
                *reinterpret_cast<const uint4*>(&g_Ql[qb + (size_t)row * CKV + c16 * 8]);
        }
    }

    float o[16][4];
#pragma unroll
    for (int v = 0; v < 16; v++)
#pragma unroll
        for (int j = 0; j < 4; j++) o[v][j] = 0.f;
    float mA = -INFINITY, mB = -INFINITY, lA = 0.f, lB = 0.f;

    const uint32_t arow = (uint32_t)(wrp * 16) + lrow + (grp & 1u) * 8u;
    const uint32_t acol = (grp >> 1) * 16u;

    for (int t = 0; t < NT; t++) {
        __syncthreads();
        // ---- load K (hi/lo) and V tiles ----
        {
            const size_t kb = ((size_t)b * NSP + (size_t)t * TN) * CKV;
#pragma unroll
            for (int i = 0; i < 4; i++) {
                const int idx = tid + i * 256;
                const int row = idx >> 4, c16 = idx & 15;
                const uint32_t so = (uint32_t)row * 272u + (uint32_t)c16 * 16u;
                *reinterpret_cast<uint4*>(sm + KHOFF + so) =
                    *reinterpret_cast<const uint4*>(&g_Kh[kb + (size_t)row * CKV + c16 * 8]);
                *reinterpret_cast<uint4*>(sm + KLOFF + so) =
                    *reinterpret_cast<const uint4*>(&g_Kl[kb + (size_t)row * CKV + c16 * 8]);
            }
#pragma unroll
            for (int i = 0; i < 4; i++) {
                const int idx = tid + i * 256;
                const int vr = idx >> 3, c = idx & 7;
                const uint32_t so = (uint32_t)vr * 144u + (uint32_t)c * 16u;
                *reinterpret_cast<uint4*>(sm + VOFF + so) =
                    *reinterpret_cast<const uint4*>(
                        &g_V[(((size_t)b * CKV) + vr) * NSP + (size_t)t * TN + c * 8]);
            }
        }
        __syncthreads();

        // ---- S = Qh.Kh^T + Ql.Kh^T + Qh.Kl^T ----
        float s[8][4];
#pragma unroll
        for (int n = 0; n < 8; n++)
#pragma unroll
            for (int j = 0; j < 4; j++) s[n][j] = 0.f;

#pragma unroll
        for (int kk = 0; kk < 8; kk++) {
            uint32_t aqh[4], aql[4];
            const uint32_t ao = arow * 272u + (uint32_t)kk * 32u + acol;
            ldsm4(aqh, smb + QHOFF + ao);
            ldsm4(aql, smb + QLOFF + ao);
#pragma unroll
            for (int nt2 = 0; nt2 < 4; nt2++) {
                uint32_t kh[4], kl[4];
                const uint32_t brow = (uint32_t)(nt2 * 16) + lrow + (grp >> 1) * 8u;
                const uint32_t bo = brow * 272u + (uint32_t)kk * 32u + (grp & 1u) * 16u;
                ldsm4(kh, smb + KHOFF + bo);
                ldsm4(kl, smb + KLOFF + bo);
                mma16816(s[2 * nt2],     aqh, kh[0], kh[1]);
                mma16816(s[2 * nt2 + 1], aqh, kh[2], kh[3]);
                mma16816(s[2 * nt2],     aql, kh[0], kh[1]);
                mma16816(s[2 * nt2 + 1], aql, kh[2], kh[3]);
                mma16816(s[2 * nt2],     aqh, kl[0], kl[1]);
                mma16816(s[2 * nt2 + 1], aqh, kl[2], kl[3]);
            }
        }

        // ---- online softmax (rows A: r1, B: r1+8) ----
        float tmA = -INFINITY, tmB = -INFINITY;
#pragma unroll
        for (int n = 0; n < 8; n++) {
            tmA = fmaxf(tmA, fmaxf(s[n][0], s[n][1]));
            tmB = fmaxf(tmB, fmaxf(s[n][2], s[n][3]));
        }
        tmA = fmaxf(tmA, __shfl_xor_sync(0xffffffffu, tmA, 1));
        tmA = fmaxf(tmA, __shfl_xor_sync(0xffffffffu, tmA, 2));
        tmB = fmaxf(tmB, __shfl_xor_sync(0xffffffffu, tmB, 1));
        tmB = fmaxf(tmB, __shfl_xor_sync(0xffffffffu, tmB, 2));

        const float nmA = fmaxf(mA, tmA), nmB = fmaxf(mB, tmB);
        const float cA = __expf(mA - nmA), cB = __expf(mB - nmB);
        mA = nmA; mB = nmB;

        uint32_t aph[4][4], apl[4][4];
        float sumA = 0.f, sumB = 0.f;
#pragma unroll
        for (int n = 0; n < 8; n++) {
            const float e0 = __expf(s[n][0] - mA);
            const float e1 = __expf(s[n][1] - mA);
            const float e2 = __expf(s[n][2] - mB);
            const float e3 = __expf(s[n][3] - mB);
            sumA += e0 + e1; sumB += e2 + e3;
            const __half h0 = __float2half_rn(e0), h1 = __float2half_rn(e1);
            const __half h2 = __float2half_rn(e2), h3 = __float2half_rn(e3);
            const float l0 = e0 - __half2float(h0), f1 = e1 - __half2float(h1);
            const float l2 = e2 - __half2float(h2), f3 = e3 - __half2float(h3);
            const int kk = n >> 1, hi = (n & 1) ? 2 : 0;
            aph[kk][hi]     = packh2(e0, e1);
            aph[kk][hi + 1] = packh2(e2, e3);
            apl[kk][hi]     = packh2(l0, f1);
            apl[kk][hi + 1] = packh2(l2, f3);
        }
        lA = lA * cA + sumA;
        lB = lB * cB + sumB;
#pragma unroll
        for (int v = 0; v < 16; v++) {
            o[v][0] *= cA; o[v][1] *= cA; o[v][2] *= cB; o[v][3] *= cB;
        }

        // ---- O += Ph.V + Pl.V ----
#pragma unroll
        for (int kk = 0; kk < 4; kk++) {
#pragma unroll
            for (int vt2 = 0; vt2 < 8; vt2++) {
                uint32_t bv[4];
                const uint32_t vrow = (uint32_t)(vt2 * 16) + lrow + (grp >> 1) * 8u;
                const uint32_t vo = vrow * 144u + (uint32_t)kk * 32u + (grp & 1u) * 16u;
                ldsm4(bv, smb + VOFF + vo);
                mma16816(o[2 * vt2],     aph[kk], bv[0], bv[1]);
                mma16816(o[2 * vt2 + 1], aph[kk], bv[2], bv[3]);
                mma16816(o[2 * vt2],     apl[kk], bv[0], bv[1]);
                mma16816(o[2 * vt2 + 1], apl[kk], bv[2], bv[3]);
            }
        }
    }

    // ---- epilogue ----
    lA += __shfl_xor_sync(0xffffffffu, lA, 1);
    lA += __shfl_xor_sync(0xffffffffu, lA, 2);
    lB += __shfl_xor_sync(0xffffffffu, lB, 1);
    lB += __shfl_xor_sync(0xffffffffu, lB, 2);
    const float invA = 1.f / lA, invB = 1.f / lB;

    const int rowA = n0 + wrp * 16 + r1;
#pragma unroll
    for (int vt = 0; vt < 16; vt++) {
        const int col = vt * 8 + quad * 2;
        float2 wa = make_float2(o[vt][0] * invA, o[vt][1] * invA);
        float2 wb = make_float2(o[vt][2] * invB, o[vt][3] * invB);
        *reinterpret_cast<float2*>(&g_Y[(((size_t)b * NSP) + rowA) * CKV + col])     = wa;
        *reinterpret_cast<float2*>(&g_Y[(((size_t)b * NSP) + rowA + 8) * CKV + col]) = wb;
    }
}

// ---------------------------------------------------------------------------
// Kernel 3: output projection (fp32, unchanged).
// ---------------------------------------------------------------------------
__global__ __launch_bounds__(256) void outproj_kernel(
    const float* __restrict__ ww, const float* __restrict__ wb,
    float* __restrict__ out)
{
    const int b  = blockIdx.z;
    const int n0 = blockIdx.x * 128;
    const int c0 = blockIdx.y * 128;

    __shared__ float As[32][129];
    __shared__ float Ws[32][129];

    const int tid = threadIdx.x;
    const int tx  = tid & 15;
    const int ty  = tid >> 4;

    float acc[8][8];
#pragma unroll
    for (int i = 0; i < 8; i++)
#pragma unroll
        for (int j = 0; j < 8; j++) acc[i][j] = 0.f;

    for (int v0 = 0; v0 < CKV; v0 += 32) {
        {
            const int vl = tid & 31;
            const int nr = tid >> 5;
#pragma unroll
            for (int r = 0; r < 16; r++) {
                const int n = nr + r * 8;
                As[vl][n] = g_Y[(((size_t)b * NSP) + n0 + n) * CKV + v0 + vl];
            }
        }
        {
            const int vl = tid & 31;
            const int cr = tid >> 5;
#pragma unroll
            for (int r = 0; r < 16; r++) {
                const int c = cr + r * 8;
                Ws[vl][c] = ww[(size_t)(c0 + c) * CKV + v0 + vl];
            }
        }
        __syncthreads();

#pragma unroll 8
        for (int v = 0; v < 32; v++) {
            float a[8], wc[8];
#pragma unroll
            for (int j = 0; j < 8; j++) a[j]  = As[v][j * 16 + tx];
#pragma unroll
            for (int i = 0; i < 8; i++) wc[i] = Ws[v][i * 16 + ty];
#pragma unroll
            for (int i = 0; i < 8; i++)
#pragma unroll
                for (int j = 0; j < 8; j++)
                    acc[i][j] = fmaf(wc[i], a[j], acc[i][j]);
        }
        __syncthreads();
    }

#pragma unroll
    for (int i = 0; i < 8; i++) {
        const int c = c0 + i * 16 + ty;
        const float bc = __ldg(&wb[c]);
#pragma unroll
        for (int j = 0; j < 8; j++) {
            out[(((size_t)b * CIN) + c) * NSP + n0 + j * 16 + tx] = acc[i][j] + bc;
        }
    }
}

// ---------------------------------------------------------------------------
extern "C" void kernel_launch(void* const* d_in, const int* in_sizes, int n_in,
                              void* d_out, int out_size)
{
    const float* x       = (const float*)d_in[0];
    const float* theta_w = (const float*)d_in[1];
    const float* theta_b = (const float*)d_in[2];
    const float* phi_w   = (const float*)d_in[3];
    const float* phi_b   = (const float*)d_in[4];
    const float* g_w     = (const float*)d_in[5];
    const float* g_b     = (const float*)d_in[6];
    const float* w_w     = (const float*)d_in[7];
    const float* w_b     = (const float*)d_in[8];
    float* out = (float*)d_out;

    proj_qkv_kernel<<<dim3(NSP / 128, 3, BATCH), 256>>>(
        x, theta_w, theta_b, phi_w, phi_b, g_w, g_b);

    cudaFuncSetAttribute(attn_hmma_kernel,
                         cudaFuncAttributeMaxDynamicSharedMemorySize,
                         (int)SMEM_ATTN);
    attn_hmma_kernel<<<dim3(NSP / 128, BATCH), 256, SMEM_ATTN>>>();

    outproj_kernel<<<dim3(NSP / 128, CIN / 128, BATCH), 256>>>(w_w, w_b, out);
}